// round 11
// baseline (speedup 1.0000x reference)
#include <cuda_runtime.h>
#include <math.h>

// Block floating-point quantization (block_size=16, mantissa_bits=8).
// v8.f32 (256-bit) loads/stores at the proven in-flight depth: 3 front-batched
// 32B loads per thread (3KB per warp-instruction batch, same bytes in flight
// as the CHUNKS=6 float4 winner, half the memory instructions, 1/4 the shuffles).
// 2 consecutive lanes share one 16-element block (single shfl_xor(1)).
// Every warp memory instruction is 1KB contiguous: 8 full 128B lines, 100% sectors.

#define TPB 256
#define CHUNKS 3
#define TILE_OCT (TPB * CHUNKS)   // 8-float groups per CTA = 768 (24KB)

__device__ __forceinline__ void ld256_cs(const float* p, float r[8]) {
    asm("ld.global.cs.v8.f32 {%0,%1,%2,%3,%4,%5,%6,%7}, [%8];"
        : "=f"(r[0]), "=f"(r[1]), "=f"(r[2]), "=f"(r[3]),
          "=f"(r[4]), "=f"(r[5]), "=f"(r[6]), "=f"(r[7])
        : "l"(p));
}

__device__ __forceinline__ void st256_cs(float* p, const float r[8]) {
    asm volatile("st.global.cs.v8.f32 [%0], {%1,%2,%3,%4,%5,%6,%7,%8};"
        :: "l"(p),
           "f"(r[0]), "f"(r[1]), "f"(r[2]), "f"(r[3]),
           "f"(r[4]), "f"(r[5]), "f"(r[6]), "f"(r[7])
        : "memory");
}

__device__ __forceinline__ float absmax8(const float r[8]) {
    float a01 = fmaxf(fabsf(r[0]), fabsf(r[1]));
    float a23 = fmaxf(fabsf(r[2]), fabsf(r[3]));
    float a45 = fmaxf(fabsf(r[4]), fabsf(r[5]));
    float a67 = fmaxf(fabsf(r[6]), fabsf(r[7]));
    return fmaxf(fmaxf(a01, a23), fmaxf(a45, a67));
}

__device__ __forceinline__ int bfp_exp(float a) {
    // floor(log2(a)) for a>0; a==0 -> 0 (all-zero block quantizes to 0 anyway).
    int ef = (__float_as_int(a) >> 23) & 0xFF;
    return (ef != 0) ? (ef - 127) : ((a > 0.0f) ? ilogbf(a) : 0);
}

__device__ __forceinline__ void bfp_quant8(float r[8], int e) {
    int eb = e - 7;   // mantissa_bits - 1 = 7
    float s  = __int_as_float((eb + 127) << 23);   // 2^(e-7)
    float is = __int_as_float((127 - eb) << 23);   // 2^(7-e)
    #pragma unroll
    for (int k = 0; k < 8; k++)
        r[k] = fminf(fmaxf(rintf(r[k] * is), -128.0f), 127.0f) * s;
}

__global__ __launch_bounds__(TPB, 6) void bfp_quant_kernel(
    const float* __restrict__ in, float* __restrict__ out, int noct)
{
    int base = blockIdx.x * TILE_OCT + threadIdx.x;   // oct index (8 floats)

    if (base + (CHUNKS - 1) * TPB < noct) {
        // ---- full-tile fast path: branch-free, 3 front-batched 256b loads ----
        float v[CHUNKS][8];
        #pragma unroll
        for (int c = 0; c < CHUNKS; c++)
            ld256_cs(in + (size_t)(base + c * TPB) * 8, v[c]);

        float a[CHUNKS];
        #pragma unroll
        for (int c = 0; c < CHUNKS; c++) a[c] = absmax8(v[c]);
        #pragma unroll
        for (int c = 0; c < CHUNKS; c++) a[c] = fmaxf(a[c], __shfl_xor_sync(0xffffffffu, a[c], 1));

        #pragma unroll
        for (int c = 0; c < CHUNKS; c++) {
            bfp_quant8(v[c], bfp_exp(a[c]));
            st256_cs(out + (size_t)(base + c * TPB) * 8, v[c]);
        }
    } else {
        // ---- tail path (last CTA only) ----
        #pragma unroll
        for (int c = 0; c < CHUNKS; c++) {
            int o = base + c * TPB;
            bool pred = o < noct;
            float v[8];
            if (pred) ld256_cs(in + (size_t)o * 8, v);
            else {
                #pragma unroll
                for (int k = 0; k < 8; k++) v[k] = 0.0f;
            }
            float a = absmax8(v);
            a = fmaxf(a, __shfl_xor_sync(0xffffffffu, a, 1));
            if (pred) {
                bfp_quant8(v, bfp_exp(a));
                st256_cs(out + (size_t)o * 8, v);
            }
        }
    }
}

extern "C" void kernel_launch(void* const* d_in, const int* in_sizes, int n_in,
                              void* d_out, int out_size)
{
    const float* x = (const float*)d_in[0];
    float* out = (float*)d_out;
    int n = in_sizes[0];             // 4*4096*4096 = 67108864
    int noct = n / 8;                // 8388608 groups of 8 floats
    int blocks = (noct + TILE_OCT - 1) / TILE_OCT;   // 10923
    bfp_quant_kernel<<<blocks, TPB>>>(x, out, noct);
}